// round 1
// baseline (speedup 1.0000x reference)
#include <cuda_runtime.h>

// Problem constants (dataset is fixed; arrays sized to these maxima)
#define NN_MAX 50000
#define NE_MAX 800000
#define FH 64

// Scratch (no allocations allowed -> __device__ globals)
__device__ float g_deg[NN_MAX];
__device__ float g_norm[NE_MAX];
__device__ float g_tx1[NN_MAX * FH];
__device__ float g_p2[NN_MAX * FH];
__device__ float g_Wc[192 * 128];   // stacked combined weights [A;B;C], row-major 192x128

__device__ __forceinline__ void red_add_v4(float* a, float x, float y, float z, float w) {
    asm volatile("red.global.add.v4.f32 [%0], {%1,%2,%3,%4};"
                 :: "l"(a), "f"(x), "f"(y), "f"(z), "f"(w) : "memory");
}

// ---------------------------------------------------------------------------
// Zero scratch: tx1, p2 (float4), deg (scalar)
__global__ void k_zero(int n) {
    int t = blockIdx.x * blockDim.x + threadIdx.x;
    int nt = n * (FH / 4);                 // float4 count per feature buffer
    float4 z = make_float4(0.f, 0.f, 0.f, 0.f);
    if (t < nt)                 ((float4*)g_tx1)[t] = z;
    else if (t < 2 * nt)        ((float4*)g_p2)[t - nt] = z;
    else if (t < 2 * nt + n)    g_deg[t - 2 * nt] = 0.f;
}

// deg[row[e]] += w[e]
__global__ void k_deg(const int* __restrict__ row, const float* __restrict__ w, int ne) {
    int e = blockIdx.x * blockDim.x + threadIdx.x;
    if (e < ne) atomicAdd(g_deg + row[e], w[e]);
}

// norm[e] = -dis[row]*w*dis[col]
__global__ void k_norm(const int* __restrict__ row, const int* __restrict__ col,
                       const float* __restrict__ w, int ne) {
    int e = blockIdx.x * blockDim.x + threadIdx.x;
    if (e < ne) {
        float dr = g_deg[row[e]], dc = g_deg[col[e]];
        float ir = dr > 0.f ? rsqrtf(dr) : 0.f;
        float ic = dc > 0.f ? rsqrtf(dc) : 0.f;
        g_norm[e] = -ir * w[e] * ic;
    }
}

// dst[col[e]] += norm[e] * src[row[e]]   (16 threads/edge, float4 each)
// pass 0: src = x (param), dst = g_tx1;  pass 1: src = g_tx1, dst = g_p2
__global__ void k_prop(const float* __restrict__ xsrc, int pass,
                       const int* __restrict__ row, const int* __restrict__ col, int ne) {
    int t = blockIdx.x * blockDim.x + threadIdx.x;
    int e = t >> 4, q = t & 15;
    if (e >= ne) return;
    const float* src = pass ? g_tx1 : xsrc;
    float* dst = pass ? g_p2 : g_tx1;
    float nm = g_norm[e];
    int r = row[e], c = col[e];
    float4 v = *(const float4*)(src + r * FH + q * 4);
    red_add_v4(dst + c * FH + q * 4, nm * v.x, nm * v.y, nm * v.z, nm * v.w);
}

// Build combined weight Wbig[192][128]:
//   rows 0..63   : Wx?[0] - Wx?[2]
//   rows 64..127 : Wx?[1]
//   rows 128..191: 2*Wx?[2]
// cols 0..63 -> z-gate (Wxz), cols 64..127 -> h-gate (Wxh)
__global__ void k_comb(const float* __restrict__ Wxz, const float* __restrict__ Wxh) {
    int t = blockIdx.x * blockDim.x + threadIdx.x;   // 0..24575
    if (t >= 192 * 128) return;
    int k = t >> 7, j = t & 127;
    const float* W = (j < 64) ? Wxz : Wxh;
    int jj = j & 63;
    float v;
    if (k < 64)       v = W[k * 64 + jj] - W[2 * 4096 + k * 64 + jj];
    else if (k < 128) v = W[4096 + (k - 64) * 64 + jj];
    else              v = 2.f * W[2 * 4096 + (k - 128) * 64 + jj];
    g_Wc[k * 128 + j] = v;
}

// ---------------------------------------------------------------------------
// Fused node-wise stage: Y = [x|tx1|p2] @ Wbig  (192->128), gates, head.
#define NPB 32
#define YSTR 130
#define SM_W (192 * 128)          // 24576 floats
#define SM_F (NPB * 192)          // 6144 floats
#define SM_Y (NPB * YSTR)         // 4160 floats
#define SMEM_BYTES ((SM_W + SM_F + SM_Y) * 4)   // 139,520 B

__global__ void k_final(const float* __restrict__ x,
                        const float* __restrict__ bxz, const float* __restrict__ bhz,
                        const float* __restrict__ bxh, const float* __restrict__ bhh,
                        const float* __restrict__ Wlin, const float* __restrict__ blin,
                        float* __restrict__ out, int n) {
    extern __shared__ float sm[];
    float* Ws = sm;
    float* Fs = sm + SM_W;
    float* Ys = Fs + SM_F;
    int tid = threadIdx.x;
    int i0 = blockIdx.x * NPB;

    // Stage weights (coalesced float4)
    for (int t = tid; t < SM_W / 4; t += 256)
        ((float4*)Ws)[t] = ((const float4*)g_Wc)[t];

    // Stage features: Fs[i][0:64)=x, [64:128)=tx1, [128:192)=p2
    for (int t = tid; t < NPB * 48; t += 256) {
        int i = t / 48, seg = t % 48;
        int node = i0 + i;
        float4 v = make_float4(0.f, 0.f, 0.f, 0.f);
        if (node < n) {
            const float* src = (seg < 16) ? (x + node * FH + seg * 4)
                             : (seg < 32) ? (g_tx1 + node * FH + (seg - 16) * 4)
                                          : (g_p2 + node * FH + (seg - 32) * 4);
            v = *(const float4*)src;
        }
        *(float4*)(Fs + i * 192 + seg * 4) = v;
    }
    __syncthreads();

    // GEMM: each thread owns output column j for 16 nodes (4 quads of 4)
    int j = tid & 127, half = tid >> 7;
    for (int q = 0; q < 4; ++q) {
        int il = half * 16 + q * 4;
        const float* F0 = Fs + il * 192;
        const float* F1 = F0 + 192;
        const float* F2 = F1 + 192;
        const float* F3 = F2 + 192;
        float a0 = 0.f, a1 = 0.f, a2 = 0.f, a3 = 0.f;
        #pragma unroll 4
        for (int k = 0; k < 192; k += 4) {
            float4 f0 = *(const float4*)(F0 + k);
            float4 f1 = *(const float4*)(F1 + k);
            float4 f2 = *(const float4*)(F2 + k);
            float4 f3 = *(const float4*)(F3 + k);
            float w0 = Ws[(k + 0) * 128 + j];
            float w1 = Ws[(k + 1) * 128 + j];
            float w2 = Ws[(k + 2) * 128 + j];
            float w3 = Ws[(k + 3) * 128 + j];
            a0 = fmaf(f0.w, w3, fmaf(f0.z, w2, fmaf(f0.y, w1, fmaf(f0.x, w0, a0))));
            a1 = fmaf(f1.w, w3, fmaf(f1.z, w2, fmaf(f1.y, w1, fmaf(f1.x, w0, a1))));
            a2 = fmaf(f2.w, w3, fmaf(f2.z, w2, fmaf(f2.y, w1, fmaf(f2.x, w0, a2))));
            a3 = fmaf(f3.w, w3, fmaf(f3.z, w2, fmaf(f3.y, w1, fmaf(f3.x, w0, a3))));
        }
        Ys[(il + 0) * YSTR + j] = a0;
        Ys[(il + 1) * YSTR + j] = a1;
        Ys[(il + 2) * YSTR + j] = a2;
        Ys[(il + 3) * YSTR + j] = a3;
    }
    __syncthreads();

    // Gates: z = sigmoid(cz + bxz + bhz); ht = tanh(ch + bxh + bhh); th = tanh((1-z)*ht)
    for (int t = tid; t < NPB * 64; t += 256) {
        int i = t >> 6, jj = t & 63;
        float cz = Ys[i * YSTR + jj]      + bxz[jj] + bhz[jj];
        float ch = Ys[i * YSTR + 64 + jj] + bxh[jj] + bhh[jj];
        float z  = 1.f / (1.f + expf(-cz));
        float ht = tanhf(ch);
        Ys[i * YSTR + jj] = tanhf((1.f - z) * ht);
    }
    __syncthreads();

    // Head: out[i][c] = sigmoid(sum_j th[i][j] * Wlin[j][c] + blin[c])
    if (tid < NPB * 2) {
        int i = tid >> 1, c = tid & 1;
        int node = i0 + i;
        if (node < n) {
            float s = blin[c];
            #pragma unroll 8
            for (int jj = 0; jj < 64; ++jj)
                s = fmaf(Ys[i * YSTR + jj], Wlin[jj * 2 + c], s);
            out[node * 2 + c] = 1.f / (1.f + expf(-s));
        }
    }
}

// ---------------------------------------------------------------------------
extern "C" void kernel_launch(void* const* d_in, const int* in_sizes, int n_in,
                              void* d_out, int out_size) {
    const float* x    = (const float*)d_in[0];
    const int*   ei   = (const int*)d_in[1];
    const float* ew   = (const float*)d_in[2];
    const float* Wxz  = (const float*)d_in[3];
    const float* bxz  = (const float*)d_in[4];
    const float* bhz  = (const float*)d_in[6];
    const float* Wxh  = (const float*)d_in[11];
    const float* bxh  = (const float*)d_in[12];
    const float* bhh  = (const float*)d_in[14];
    const float* Wlin = (const float*)d_in[15];
    const float* blin = (const float*)d_in[16];
    float* out = (float*)d_out;

    int n  = in_sizes[0] / FH;
    int ne = in_sizes[2];
    const int* row = ei;
    const int* col = ei + ne;

    cudaFuncSetAttribute(k_final, cudaFuncAttributeMaxDynamicSharedMemorySize, SMEM_BYTES);

    int zthreads = 2 * n * (FH / 4) + n;
    k_zero<<<(zthreads + 255) / 256, 256>>>(n);
    k_deg<<<(ne + 255) / 256, 256>>>(row, ew, ne);
    k_norm<<<(ne + 255) / 256, 256>>>(row, col, ew, ne);
    k_prop<<<(ne * 16 + 255) / 256, 256>>>(x, 0, row, col, ne);
    k_prop<<<(ne * 16 + 255) / 256, 256>>>(x, 1, row, col, ne);
    k_comb<<<96, 256>>>(Wxz, Wxh);
    k_final<<<(n + NPB - 1) / NPB, 256, SMEM_BYTES>>>(x, bxz, bhz, bxh, bhh, Wlin, blin, out, n);
}

// round 2
// speedup vs baseline: 1.0136x; 1.0136x over previous
#include <cuda_runtime.h>

#define NN_MAX 50000
#define NE_MAX 800000
#define FH 64
#define SCAN_BLK 256

// Scratch (__device__ globals; no allocation allowed)
__device__ float g_deg[NN_MAX];
__device__ int   g_cnt[NN_MAX];
__device__ int   g_start[NN_MAX];
__device__ int   g_cursor[NN_MAX];
__device__ int   g_bsum[SCAN_BLK];
__device__ int   g_boff[SCAN_BLK];
__device__ float2 g_es[NE_MAX];          // packed (row-as-float-bits, norm), bucketed by col
__device__ float g_tx1[NN_MAX * FH];
__device__ float g_p2[NN_MAX * FH];
__device__ float g_Wc[192 * 128];

// ---------------------------------------------------------------------------
__global__ void k_zero(int n) {
    int t = blockIdx.x * blockDim.x + threadIdx.x;
    if (t < n) { g_deg[t] = 0.f; g_cnt[t] = 0; }
}

// deg[row] += w ; cnt[col] += 1   (fused histogram)
__global__ void k_degcnt(const int* __restrict__ row, const int* __restrict__ col,
                         const float* __restrict__ w, int ne) {
    int e = blockIdx.x * blockDim.x + threadIdx.x;
    if (e < ne) {
        atomicAdd(g_deg + row[e], w[e]);
        atomicAdd(g_cnt + col[e], 1);
    }
}

// ---- 3-stage exclusive scan of cnt -> start (n <= 65536) ----
__global__ void k_scan1(int n) {          // per-block sums
    __shared__ int s[SCAN_BLK];
    int i = blockIdx.x * SCAN_BLK + threadIdx.x;
    int v = (i < n) ? g_cnt[i] : 0;
    s[threadIdx.x] = v; __syncthreads();
    for (int o = SCAN_BLK / 2; o > 0; o >>= 1) {
        if (threadIdx.x < o) s[threadIdx.x] += s[threadIdx.x + o];
        __syncthreads();
    }
    if (threadIdx.x == 0) g_bsum[blockIdx.x] = s[0];
}
__global__ void k_scan2(int nblk) {       // scan of block sums (1 block)
    __shared__ int s[SCAN_BLK];
    int t = threadIdx.x;
    int v = (t < nblk) ? g_bsum[t] : 0;
    s[t] = v; __syncthreads();
    for (int o = 1; o < SCAN_BLK; o <<= 1) {
        int u = (t >= o) ? s[t - o] : 0;
        __syncthreads(); s[t] += u; __syncthreads();
    }
    g_boff[t] = s[t] - v;                 // exclusive
}
__global__ void k_scan3(int n) {          // within-block exclusive scan + offset
    __shared__ int s[SCAN_BLK];
    int t = threadIdx.x;
    int i = blockIdx.x * SCAN_BLK + t;
    int v = (i < n) ? g_cnt[i] : 0;
    s[t] = v; __syncthreads();
    for (int o = 1; o < SCAN_BLK; o <<= 1) {
        int u = (t >= o) ? s[t - o] : 0;
        __syncthreads(); s[t] += u; __syncthreads();
    }
    if (i < n) {
        int st = g_boff[blockIdx.x] + s[t] - v;
        g_start[i] = st;
        g_cursor[i] = st;
    }
}

// Scatter edges into destination buckets; norm computed inline (fuses k_norm)
__global__ void k_scatter(const int* __restrict__ row, const int* __restrict__ col,
                          const float* __restrict__ w, int ne) {
    int e = blockIdx.x * blockDim.x + threadIdx.x;
    if (e >= ne) return;
    int r = row[e], c = col[e];
    float dr = g_deg[r], dc = g_deg[c];
    float ir = dr > 0.f ? rsqrtf(dr) : 0.f;
    float ic = dc > 0.f ? rsqrtf(dc) : 0.f;
    float nm = -ir * w[e] * ic;
    int pos = atomicAdd(g_cursor + c, 1);
    g_es[pos] = make_float2(__int_as_float(r), nm);
}

// Atomic-free propagation: 16 threads per dst node, float4 quad each.
// pass 0: src = x -> g_tx1 ; pass 1: src = g_tx1 -> g_p2
__global__ void k_gather(const float* __restrict__ xsrc, int pass, int n) {
    int t = blockIdx.x * blockDim.x + threadIdx.x;
    int node = t >> 4, q = t & 15;
    if (node >= n) return;
    const float* src = pass ? g_tx1 : xsrc;
    float* dst = pass ? g_p2 : g_tx1;
    int beg = g_start[node], dg = g_cnt[node];
    float4 acc = make_float4(0.f, 0.f, 0.f, 0.f);
    for (int k = 0; k < dg; ++k) {
        float2 ep = g_es[beg + k];                 // broadcast across the 16 threads
        int r = __float_as_int(ep.x);
        float4 v = *(const float4*)(src + r * FH + q * 4);
        acc.x = fmaf(ep.y, v.x, acc.x);
        acc.y = fmaf(ep.y, v.y, acc.y);
        acc.z = fmaf(ep.y, v.z, acc.z);
        acc.w = fmaf(ep.y, v.w, acc.w);
    }
    *(float4*)(dst + node * FH + q * 4) = acc;
}

// Combined weight Wbig[192][128]: rows [W0-W2 ; W1 ; 2*W2], cols [z | h]
__global__ void k_comb(const float* __restrict__ Wxz, const float* __restrict__ Wxh) {
    int t = blockIdx.x * blockDim.x + threadIdx.x;
    if (t >= 192 * 128) return;
    int k = t >> 7, j = t & 127;
    const float* W = (j < 64) ? Wxz : Wxh;
    int jj = j & 63;
    float v;
    if (k < 64)       v = W[k * 64 + jj] - W[2 * 4096 + k * 64 + jj];
    else if (k < 128) v = W[4096 + (k - 64) * 64 + jj];
    else              v = 2.f * W[2 * 4096 + (k - 128) * 64 + jj];
    g_Wc[k * 128 + j] = v;
}

// ---------------------------------------------------------------------------
// Fused node-wise stage: Y = [x|tx1|p2] @ Wbig (192->128), gates, head.
#define NPB 32
#define YSTR 130
#define SM_W (192 * 128)
#define SM_F (NPB * 192)
#define SM_Y (NPB * YSTR)
#define SMEM_BYTES ((SM_W + SM_F + SM_Y) * 4)

__global__ void k_final(const float* __restrict__ x,
                        const float* __restrict__ bxz, const float* __restrict__ bhz,
                        const float* __restrict__ bxh, const float* __restrict__ bhh,
                        const float* __restrict__ Wlin, const float* __restrict__ blin,
                        float* __restrict__ out, int n) {
    extern __shared__ float sm[];
    float* Ws = sm;
    float* Fs = sm + SM_W;
    float* Ys = Fs + SM_F;
    int tid = threadIdx.x;
    int i0 = blockIdx.x * NPB;

    for (int t = tid; t < SM_W / 4; t += 256)
        ((float4*)Ws)[t] = ((const float4*)g_Wc)[t];

    for (int t = tid; t < NPB * 48; t += 256) {
        int i = t / 48, seg = t % 48;
        int node = i0 + i;
        float4 v = make_float4(0.f, 0.f, 0.f, 0.f);
        if (node < n) {
            const float* src = (seg < 16) ? (x + node * FH + seg * 4)
                             : (seg < 32) ? (g_tx1 + node * FH + (seg - 16) * 4)
                                          : (g_p2 + node * FH + (seg - 32) * 4);
            v = *(const float4*)src;
        }
        *(float4*)(Fs + i * 192 + seg * 4) = v;
    }
    __syncthreads();

    int j = tid & 127, half = tid >> 7;
    for (int q = 0; q < 4; ++q) {
        int il = half * 16 + q * 4;
        const float* F0 = Fs + il * 192;
        const float* F1 = F0 + 192;
        const float* F2 = F1 + 192;
        const float* F3 = F2 + 192;
        float a0 = 0.f, a1 = 0.f, a2 = 0.f, a3 = 0.f;
        #pragma unroll 4
        for (int k = 0; k < 192; k += 4) {
            float4 f0 = *(const float4*)(F0 + k);
            float4 f1 = *(const float4*)(F1 + k);
            float4 f2 = *(const float4*)(F2 + k);
            float4 f3 = *(const float4*)(F3 + k);
            float w0 = Ws[(k + 0) * 128 + j];
            float w1 = Ws[(k + 1) * 128 + j];
            float w2 = Ws[(k + 2) * 128 + j];
            float w3 = Ws[(k + 3) * 128 + j];
            a0 = fmaf(f0.w, w3, fmaf(f0.z, w2, fmaf(f0.y, w1, fmaf(f0.x, w0, a0))));
            a1 = fmaf(f1.w, w3, fmaf(f1.z, w2, fmaf(f1.y, w1, fmaf(f1.x, w0, a1))));
            a2 = fmaf(f2.w, w3, fmaf(f2.z, w2, fmaf(f2.y, w1, fmaf(f2.x, w0, a2))));
            a3 = fmaf(f3.w, w3, fmaf(f3.z, w2, fmaf(f3.y, w1, fmaf(f3.x, w0, a3))));
        }
        Ys[(il + 0) * YSTR + j] = a0;
        Ys[(il + 1) * YSTR + j] = a1;
        Ys[(il + 2) * YSTR + j] = a2;
        Ys[(il + 3) * YSTR + j] = a3;
    }
    __syncthreads();

    for (int t = tid; t < NPB * 64; t += 256) {
        int i = t >> 6, jj = t & 63;
        float cz = Ys[i * YSTR + jj]      + bxz[jj] + bhz[jj];
        float ch = Ys[i * YSTR + 64 + jj] + bxh[jj] + bhh[jj];
        float z  = 1.f / (1.f + expf(-cz));
        float ht = tanhf(ch);
        Ys[i * YSTR + jj] = tanhf((1.f - z) * ht);
    }
    __syncthreads();

    if (tid < NPB * 2) {
        int i = tid >> 1, c = tid & 1;
        int node = i0 + i;
        if (node < n) {
            float s = blin[c];
            #pragma unroll 8
            for (int jj = 0; jj < 64; ++jj)
                s = fmaf(Ys[i * YSTR + jj], Wlin[jj * 2 + c], s);
            out[node * 2 + c] = 1.f / (1.f + expf(-s));
        }
    }
}

// ---------------------------------------------------------------------------
extern "C" void kernel_launch(void* const* d_in, const int* in_sizes, int n_in,
                              void* d_out, int out_size) {
    const float* x    = (const float*)d_in[0];
    const int*   ei   = (const int*)d_in[1];
    const float* ew   = (const float*)d_in[2];
    const float* Wxz  = (const float*)d_in[3];
    const float* bxz  = (const float*)d_in[4];
    const float* bhz  = (const float*)d_in[6];
    const float* Wxh  = (const float*)d_in[11];
    const float* bxh  = (const float*)d_in[12];
    const float* bhh  = (const float*)d_in[14];
    const float* Wlin = (const float*)d_in[15];
    const float* blin = (const float*)d_in[16];
    float* out = (float*)d_out;

    int n  = in_sizes[0] / FH;
    int ne = in_sizes[2];
    const int* row = ei;
    const int* col = ei + ne;
    int nblk = (n + SCAN_BLK - 1) / SCAN_BLK;   // <= 256 for n <= 65536

    cudaFuncSetAttribute(k_final, cudaFuncAttributeMaxDynamicSharedMemorySize, SMEM_BYTES);

    k_zero<<<(n + 255) / 256, 256>>>(n);
    k_degcnt<<<(ne + 255) / 256, 256>>>(row, col, ew, ne);
    k_scan1<<<nblk, SCAN_BLK>>>(n);
    k_scan2<<<1, SCAN_BLK>>>(nblk);
    k_scan3<<<nblk, SCAN_BLK>>>(n);
    k_scatter<<<(ne + 255) / 256, 256>>>(row, col, ew, ne);
    k_gather<<<(n * 16 + 255) / 256, 256>>>(x, 0, n);
    k_gather<<<(n * 16 + 255) / 256, 256>>>(x, 1, n);
    k_comb<<<96, 256>>>(Wxz, Wxh);
    k_final<<<(n + NPB - 1) / NPB, 256, SMEM_BYTES>>>(x, bxz, bhz, bxh, bhh, Wlin, blin, out, n);
}

// round 4
// speedup vs baseline: 1.7025x; 1.6796x over previous
#include <cuda_runtime.h>
#include <cstdint>

#define NN_MAX 50000
#define NE_MAX 800000
#define FH 64

// Scratch
__device__ float g_deg[NN_MAX];
__device__ float g_norm[NE_MAX];
__device__ float g_tx1[NN_MAX * FH];
__device__ float g_p2[NN_MAX * FH];
__device__ float g_Wc[192 * 136];   // combined weights, [k][n] with stride 136, tf32-rounded

__device__ __forceinline__ void red_add_v4(float* a, float x, float y, float z, float w) {
    asm volatile("red.global.add.v4.f32 [%0], {%1,%2,%3,%4};"
                 :: "l"(a), "f"(x), "f"(y), "f"(z), "f"(w) : "memory");
}
__device__ __forceinline__ uint32_t f2tf32(float f) {
    uint32_t u;
    asm("cvt.rna.tf32.f32 %0, %1;" : "=r"(u) : "f"(f));
    return u;
}
__device__ __forceinline__ float fast_sigmoid(float x) { return 1.f / (1.f + __expf(-x)); }
__device__ __forceinline__ float fast_tanh(float x) {
    float t = __expf(-2.f * fabsf(x));
    float r = (1.f - t) / (1.f + t);
    return copysignf(r, x);
}

// ---------------------------------------------------------------------------
__global__ void k_zero(int n) {
    int t = blockIdx.x * blockDim.x + threadIdx.x;
    int nt = n * (FH / 4);
    float4 z = make_float4(0.f, 0.f, 0.f, 0.f);
    if (t < nt)              ((float4*)g_tx1)[t] = z;
    else if (t < 2 * nt)     ((float4*)g_p2)[t - nt] = z;
    else if (t < 2 * nt + n) g_deg[t - 2 * nt] = 0.f;
}

__global__ void k_deg(const int* __restrict__ row, const float* __restrict__ w, int ne) {
    int e = blockIdx.x * blockDim.x + threadIdx.x;
    if (e < ne) atomicAdd(g_deg + row[e], w[e]);
}

// pass 0: compute norm inline, x -> tx1
__global__ void k_prop0(const float* __restrict__ x, const int* __restrict__ row,
                        const int* __restrict__ col, const float* __restrict__ w, int ne) {
    int t = blockIdx.x * blockDim.x + threadIdx.x;
    int e = t >> 4, q = t & 15;
    if (e >= ne) return;
    int r = row[e], c = col[e];
    float dr = g_deg[r], dc = g_deg[c];
    float ir = dr > 0.f ? rsqrtf(dr) : 0.f;
    float ic = dc > 0.f ? rsqrtf(dc) : 0.f;
    float nm = -ir * w[e] * ic;
    if (q == 0) g_norm[e] = nm;
    float4 v = *(const float4*)(x + r * FH + q * 4);
    red_add_v4(g_tx1 + c * FH + q * 4, nm * v.x, nm * v.y, nm * v.z, nm * v.w);
}

// pass 1: tx1 -> p2 using stored norm
__global__ void k_prop1(const int* __restrict__ row, const int* __restrict__ col, int ne) {
    int t = blockIdx.x * blockDim.x + threadIdx.x;
    int e = t >> 4, q = t & 15;
    if (e >= ne) return;
    float nm = g_norm[e];
    int r = row[e], c = col[e];
    float4 v = *(const float4*)(g_tx1 + r * FH + q * 4);
    red_add_v4(g_p2 + c * FH + q * 4, nm * v.x, nm * v.y, nm * v.z, nm * v.w);
}

// Combined weights B[k][n] (stride 136), tf32-rounded:
//   k<64: W0-W2 ; 64..127: W1 ; 128..191: 2*W2 ; n<64 -> Wxz else Wxh
__global__ void k_comb(const float* __restrict__ Wxz, const float* __restrict__ Wxh) {
    int t = blockIdx.x * blockDim.x + threadIdx.x;
    if (t >= 192 * 128) return;
    int k = t >> 7, j = t & 127;
    const float* W = (j < 64) ? Wxz : Wxh;
    int jj = j & 63;
    float v;
    if (k < 64)       v = W[k * 64 + jj] - W[2 * 4096 + k * 64 + jj];
    else if (k < 128) v = W[4096 + (k - 64) * 64 + jj];
    else              v = 2.f * W[2 * 4096 + (k - 128) * 64 + jj];
    g_Wc[k * 136 + j] = __uint_as_float(f2tf32(v));
}

// ---------------------------------------------------------------------------
// k_final: per block 128 nodes; D[128x128] = A[128x192] @ B[192x128] via
// mma.sync.m16n8k8.tf32 (tensor pipe), then gates + head.
#define A_STR 196
#define B_STR 136
#define Y_STR 132
#define SM_BZ   0
#define SM_BH   256
#define SM_WLIN 512
#define SM_A    1024
#define SM_B    (SM_A + 128 * A_STR * 4)          // 1024 + 100352 = 101376
#define SMEM_BYTES (SM_B + 192 * B_STR * 4)       // 101376 + 104448 = 205824

__device__ __forceinline__ void mma8(float* c, const uint32_t* a, const uint32_t* b) {
    asm volatile("mma.sync.aligned.m16n8k8.row.col.f32.tf32.tf32.f32 "
                 "{%0,%1,%2,%3}, {%4,%5,%6,%7}, {%8,%9}, {%0,%1,%2,%3};"
                 : "+f"(c[0]), "+f"(c[1]), "+f"(c[2]), "+f"(c[3])
                 : "r"(a[0]), "r"(a[1]), "r"(a[2]), "r"(a[3]), "r"(b[0]), "r"(b[1]));
}

__global__ void __launch_bounds__(256, 1)
k_final(const float* __restrict__ x,
        const float* __restrict__ bxz, const float* __restrict__ bhz,
        const float* __restrict__ bxh, const float* __restrict__ bhh,
        const float* __restrict__ Wlin, const float* __restrict__ blin,
        float* __restrict__ out, int n) {
    extern __shared__ __align__(16) char smem[];
    float* sBz = (float*)(smem + SM_BZ);
    float* sBh = (float*)(smem + SM_BH);
    float* sWl = (float*)(smem + SM_WLIN);
    float* As  = (float*)(smem + SM_A);
    float* Bs  = (float*)(smem + SM_B);
    const uint32_t* Au = (const uint32_t*)As;
    const uint32_t* Bu = (const uint32_t*)Bs;

    int tid = threadIdx.x, wid = tid >> 5, lane = tid & 31;
    int blk = blockIdx.x;

    // Stage B (tf32-rounded image, linear float4 copy: 192*136/4 = 6528)
    for (int t = tid; t < 6528; t += 256)
        ((float4*)Bs)[t] = ((const float4*)g_Wc)[t];

    // Stage A with tf32 rounding: row m = node, k = [x|tx1|p2]
    for (int idx = tid; idx < 128 * 48; idx += 256) {
        int m = idx / 48, seg = idx % 48;
        int g = blk * 128 + m;
        float4 v = make_float4(0.f, 0.f, 0.f, 0.f);
        if (g < n) {
            const float* src = (seg < 16) ? (x + g * FH + seg * 4)
                             : (seg < 32) ? (g_tx1 + g * FH + (seg - 16) * 4)
                                          : (g_p2 + g * FH + (seg - 32) * 4);
            v = *(const float4*)src;
        }
        float4 o;
        o.x = __uint_as_float(f2tf32(v.x));
        o.y = __uint_as_float(f2tf32(v.y));
        o.z = __uint_as_float(f2tf32(v.z));
        o.w = __uint_as_float(f2tf32(v.w));
        *(float4*)(As + m * A_STR + seg * 4) = o;
    }

    if (tid < 64) {
        sBz[tid] = bxz[tid] + bhz[tid];
        sBh[tid] = bxh[tid] + bhh[tid];
    }
    if (tid < 128) sWl[tid] = Wlin[tid];
    __syncthreads();

    // Warp tile: mw in {0,1} -> 64 rows, nw in {0..3} -> 32 cols
    int mw = wid >> 2, nw = wid & 3;
    int g8 = lane >> 2, t4 = lane & 3;
    int m0 = mw * 64, n0 = nw * 32;

    float acc[4][4][4];
    #pragma unroll
    for (int mt = 0; mt < 4; ++mt)
        #pragma unroll
        for (int nt = 0; nt < 4; ++nt)
            #pragma unroll
            for (int e = 0; e < 4; ++e) acc[mt][nt][e] = 0.f;

    #pragma unroll 4
    for (int ks = 0; ks < 24; ++ks) {
        int k0 = ks * 8;
        uint32_t a[4][4];
        #pragma unroll
        for (int mt = 0; mt < 4; ++mt) {
            int r0 = m0 + mt * 16;
            a[mt][0] = Au[(r0 + g8)     * A_STR + k0 + t4];
            a[mt][1] = Au[(r0 + g8 + 8) * A_STR + k0 + t4];
            a[mt][2] = Au[(r0 + g8)     * A_STR + k0 + t4 + 4];
            a[mt][3] = Au[(r0 + g8 + 8) * A_STR + k0 + t4 + 4];
        }
        uint32_t b[4][2];
        #pragma unroll
        for (int nt = 0; nt < 4; ++nt) {
            int c0 = n0 + nt * 8;
            b[nt][0] = Bu[(k0 + t4)     * B_STR + c0 + g8];
            b[nt][1] = Bu[(k0 + t4 + 4) * B_STR + c0 + g8];
        }
        #pragma unroll
        for (int mt = 0; mt < 4; ++mt)
            #pragma unroll
            for (int nt = 0; nt < 4; ++nt)
                mma8(acc[mt][nt], a[mt], b[nt]);
    }
    __syncthreads();   // done reading As/Bs; reuse As region as Y

    float* Ys = As;    // [128][Y_STR]
    #pragma unroll
    for (int mt = 0; mt < 4; ++mt) {
        #pragma unroll
        for (int nt = 0; nt < 4; ++nt) {
            int r = m0 + mt * 16 + g8;
            int c = n0 + nt * 8 + 2 * t4;
            Ys[r * Y_STR + c]           = acc[mt][nt][0];
            Ys[r * Y_STR + c + 1]       = acc[mt][nt][1];
            Ys[(r + 8) * Y_STR + c]     = acc[mt][nt][2];
            Ys[(r + 8) * Y_STR + c + 1] = acc[mt][nt][3];
        }
    }
    __syncthreads();

    // Gates: th = tanh((1-sigmoid(cz)) * tanh(ch))
    for (int t = tid; t < 128 * 64; t += 256) {
        int i = t >> 6, j = t & 63;
        float cz = Ys[i * Y_STR + j]      + sBz[j];
        float ch = Ys[i * Y_STR + 64 + j] + sBh[j];
        float z  = fast_sigmoid(cz);
        float ht = fast_tanh(ch);
        Ys[i * Y_STR + j] = fast_tanh((1.f - z) * ht);
    }
    __syncthreads();

    // Head
    {
        int i = tid >> 1, c = tid & 1;
        int g = blk * 128 + i;
        if (g < n) {
            float s = blin[c];
            #pragma unroll 8
            for (int jj = 0; jj < 64; ++jj)
                s = fmaf(Ys[i * Y_STR + jj], sWl[2 * jj + c], s);
            out[g * 2 + c] = fast_sigmoid(s);
        }
    }
}

// ---------------------------------------------------------------------------
extern "C" void kernel_launch(void* const* d_in, const int* in_sizes, int n_in,
                              void* d_out, int out_size) {
    const float* x    = (const float*)d_in[0];
    const int*   ei   = (const int*)d_in[1];
    const float* ew   = (const float*)d_in[2];
    const float* Wxz  = (const float*)d_in[3];
    const float* bxz  = (const float*)d_in[4];
    const float* bhz  = (const float*)d_in[6];
    const float* Wxh  = (const float*)d_in[11];
    const float* bxh  = (const float*)d_in[12];
    const float* bhh  = (const float*)d_in[14];
    const float* Wlin = (const float*)d_in[15];
    const float* blin = (const float*)d_in[16];
    float* out = (float*)d_out;

    int n  = in_sizes[0] / FH;
    int ne = in_sizes[2];
    const int* row = ei;
    const int* col = ei + ne;

    cudaFuncSetAttribute(k_final, cudaFuncAttributeMaxDynamicSharedMemorySize, SMEM_BYTES);

    int zthreads = 2 * n * (FH / 4) + n;
    k_zero<<<(zthreads + 255) / 256, 256>>>(n);
    k_deg<<<(ne + 255) / 256, 256>>>(row, ew, ne);
    k_prop0<<<(ne * 16 + 255) / 256, 256>>>(x, row, col, ew, ne);
    k_prop1<<<(ne * 16 + 255) / 256, 256>>>(row, col, ne);
    k_comb<<<96, 256>>>(Wxz, Wxh);
    k_final<<<(n + 127) / 128, 256, SMEM_BYTES>>>(x, bxz, bhz, bxh, bhh, Wlin, blin, out, n);
}